// round 12
// baseline (speedup 1.0000x reference)
#include <cuda_runtime.h>
#include <cuda_fp16.h>

// Problem constants (reference: B=2048, T=50, N=100, V=50000, D=512)
#define D_DIM 512
#define T_TGT 50
#define N_NOI 100
#define K_TOT 150
#define V_MAX 50000
#define MAX_B 4096
#define WPB   10            // warps per block
#define RPW   15            // rows per warp (10*15 = 150)
#define NTHR  (WPB * 32)    // 320

// Scratch (__device__ globals: allocation APIs are forbidden)
__device__ signed char   g_Wq[(size_t)V_MAX * D_DIM];  // 25.6 MB int8 copy of W
__device__ float         g_Wscale[V_MAX];              // per-row W scale
__device__ signed char   g_fq[(size_t)MAX_B * D_DIM];  // int8 quantized features
__device__ float         g_fscale[MAX_B];              // per-example feature scale
__device__ float         g_partials[MAX_B];
__device__ int           g_idx_stride;                 // 1 = int32 indices, 2 = int64 low word
__device__ unsigned int  g_count;                      // zero-init; reset by last block each call

__device__ __forceinline__ float log_sigmoid(float x) {
    return fminf(x, 0.0f) - __logf(1.0f + __expf(-fabsf(x)));
}

__device__ __forceinline__ unsigned pack4(float x, float y, float z, float w, float inv) {
    int b0 = __float2int_rn(x * inv);
    int b1 = __float2int_rn(y * inv);
    int b2 = __float2int_rn(z * inv);
    int b3 = __float2int_rn(w * inv);
    return (unsigned)(b0 & 0xFF) | ((unsigned)(b1 & 0xFF) << 8) |
           ((unsigned)(b2 & 0xFF) << 16) | ((unsigned)b3 << 24);
}

// One warp quantizes one length-512 fp32 vector to int8 with a single scale.
// Lane owns elements [16*lane, 16*lane+16).
__device__ __forceinline__ void quant_row_warp(const float* __restrict__ src,
                                               signed char* __restrict__ dst,
                                               float* __restrict__ scale_out,
                                               int lane, bool streaming)
{
    const float4* s4 = reinterpret_cast<const float4*>(src);
    float4 v[4];
    #pragma unroll
    for (int j = 0; j < 4; j++)
        v[j] = streaming ? __ldcs(&s4[4 * lane + j]) : s4[4 * lane + j];

    float m = 0.0f;
    #pragma unroll
    for (int j = 0; j < 4; j++) {
        m = fmaxf(m, fabsf(v[j].x)); m = fmaxf(m, fabsf(v[j].y));
        m = fmaxf(m, fabsf(v[j].z)); m = fmaxf(m, fabsf(v[j].w));
    }
    #pragma unroll
    for (int o = 16; o > 0; o >>= 1)
        m = fmaxf(m, __shfl_xor_sync(0xFFFFFFFFu, m, o));

    const float inv = (m > 0.0f) ? 127.0f / m : 0.0f;

    uint4 o4;
    o4.x = pack4(v[0].x, v[0].y, v[0].z, v[0].w, inv);
    o4.y = pack4(v[1].x, v[1].y, v[1].z, v[1].w, inv);
    o4.z = pack4(v[2].x, v[2].y, v[2].z, v[2].w, inv);
    o4.w = pack4(v[3].x, v[3].y, v[3].z, v[3].w, inv);
    reinterpret_cast<uint4*>(dst)[lane] = o4;

    if (lane == 0)
        *scale_out = m * (1.0f / 127.0f);
}

// Blocks [0, nRowBlocks): quantize W rows. Blocks [nRowBlocks, ...): quantize features.
__global__ void __launch_bounds__(256)
nsl_convert_kernel(const float* __restrict__ W, const float* __restrict__ features,
                   const int* __restrict__ t32, int nRows, int nRowBlocks, int B)
{
    if (blockIdx.x == 0 && threadIdx.x == 0) {
        int all_zero = 1;
        #pragma unroll
        for (int i = 0; i < 8; i++)
            if (t32[2 * i + 1] != 0) all_zero = 0;
        g_idx_stride = all_zero ? 2 : 1;   // int64 little-endian => odd words are 0
    }

    const int warp = threadIdx.x >> 5;
    const int lane = threadIdx.x & 31;

    if ((int)blockIdx.x < nRowBlocks) {
        const int row = blockIdx.x * 8 + warp;
        if (row < nRows)
            quant_row_warp(W + (size_t)row * D_DIM,
                           g_Wq + (size_t)row * D_DIM,
                           &g_Wscale[row], lane, true);
    } else {
        const int ex = (blockIdx.x - nRowBlocks) * 8 + warp;
        if (ex < B)
            quant_row_warp(features + (size_t)ex * D_DIM,
                           g_fq + (size_t)ex * D_DIM,
                           &g_fscale[ex], lane, false);
    }
}

// 16 int8 x 16 int8 exact dot via 4 dp4a.
__device__ __forceinline__ int dot16(uint4 w, const int* fq) {
    int acc = 0;
    acc = __dp4a((int)w.x, fq[0], acc);
    acc = __dp4a((int)w.y, fq[1], acc);
    acc = __dp4a((int)w.z, fq[2], acc);
    acc = __dp4a((int)w.w, fq[3], acc);
    return acc;
}

// min-blocks=2 gives ptxas a ~102-reg budget: keep all 15 row loads live.
__global__ void __launch_bounds__(NTHR, 2)
nsl_main_kernel(const int* __restrict__ targets,
                const int* __restrict__ noises,
                float* __restrict__ out, int B)
{
    const int b    = blockIdx.x;
    const int tid  = threadIdx.x;
    const int warp = tid >> 5;
    const int lane = tid & 31;
    const int str  = g_idx_stride;

    __shared__ float wsum[WPB];
    __shared__ int   is_last;

    // Prologue: one LDG.128 of pre-quantized features + one scalar scale load.
    int fq[4];
    {
        uint4 f = reinterpret_cast<const uint4*>(g_fq + (size_t)b * D_DIM)[lane];
        fq[0] = (int)f.x; fq[1] = (int)f.y; fq[2] = (int)f.z; fq[3] = (int)f.w;
    }
    const float sf = g_fscale[b];

    const int* tg = targets + (size_t)b * T_TGT * str;
    const int* ns = noises  + (size_t)b * N_NOI * str;

    // Warp w owns rows k in [15w, 15w+15). Lane r (r<15) preloads row 15w+r's index.
    int myidx = 0;
    if (lane < RPW) {
        int k = warp * RPW + lane;
        myidx = (k < T_TGT) ? tg[k * str] : ns[(k - T_TGT) * str];
    }

    // ---- Phase 1: issue ALL 15 LDG.128 into a live register array ----
    uint4 a[RPW];
    #pragma unroll
    for (int q = 0; q < RPW; q++) {
        int idx = __shfl_sync(0xFFFFFFFFu, myidx, q);
        a[q] = __ldcg(&reinterpret_cast<const uint4*>(g_Wq + (size_t)idx * D_DIM)[lane]);
    }

    // ---- Phase 2: consume ----
    int s[RPW];
    #pragma unroll
    for (int q = 0; q < RPW; q++)
        s[q] = dot16(a[q], fq);

    // ---- 15 single-instruction warp reductions (REDUX.SUM, result in all lanes) ----
    int t[RPW];
    #pragma unroll
    for (int q = 0; q < RPW; q++)
        t[q] = __reduce_add_sync(0xFFFFFFFFu, s[q]);

    // Lane r takes row r's total; one parallel logsigmoid pass covers all 15 rows.
    int v = t[0];
    #pragma unroll
    for (int q = 1; q < RPW; q++)
        if (lane == q) v = t[q];

    float local = 0.0f;
    if (lane < RPW) {
        float sw  = g_Wscale[myidx];          // this lane's own row index
        int   k   = warp * RPW + lane;
        float sgn = (k < T_TGT) ? 1.0f : -1.0f;
        local = log_sigmoid(sgn * (float)v * (sw * sf));
    }

    // Sum the 15 lane values within the warp.
    #pragma unroll
    for (int o = 16; o > 0; o >>= 1)
        local += __shfl_xor_sync(0xFFFFFFFFu, local, o);

    if (lane == 0) wsum[warp] = local;
    __syncthreads();

    if (tid == 0) {
        float sum = 0.0f;
        #pragma unroll
        for (int w = 0; w < WPB; w++) sum += wsum[w];
        g_partials[b] = sum;
        __threadfence();
        unsigned c = atomicAdd(&g_count, 1u);
        is_last = (c == (unsigned)(gridDim.x - 1)) ? 1 : 0;
    }
    __syncthreads();

    // Last finished block performs the deterministic final reduction (256 threads).
    if (is_last) {
        __shared__ float red[256];
        __threadfence();
        if (tid < 256) {
            float sum = 0.0f;
            for (int i = tid; i < B; i += 256)
                sum += g_partials[i];
            red[tid] = sum;
        }
        __syncthreads();
        #pragma unroll
        for (int stride = 128; stride > 0; stride >>= 1) {
            if (tid < stride) red[tid] += red[tid + stride];
            __syncthreads();
        }
        if (tid == 0) {
            out[0] = -red[0] / (float)K_TOT;
            g_count = 0;   // reset for next graph replay
        }
    }
}

extern "C" void kernel_launch(void* const* d_in, const int* in_sizes, int n_in,
                              void* d_out, int out_size)
{
    const float* features = (const float*)d_in[0];
    const int*   targets  = (const int*)d_in[1];
    const int*   noises   = (const int*)d_in[2];
    const float* W        = (const float*)d_in[3];

    const int B     = in_sizes[0] / D_DIM;        // 2048
    const int nRows = in_sizes[3] / D_DIM;        // 50000

    const int nRowBlocks = (nRows + 7) / 8;       // 6250
    const int nFeaBlocks = (B + 7) / 8;           // 256

    nsl_convert_kernel<<<nRowBlocks + nFeaBlocks, 256>>>(W, features, targets,
                                                         nRows, nRowBlocks, B);
    nsl_main_kernel<<<B, NTHR>>>(targets, noises, (float*)d_out, B);
}

// round 13
// speedup vs baseline: 1.1039x; 1.1039x over previous
#include <cuda_runtime.h>
#include <cuda_fp16.h>

// Problem constants (reference: B=2048, T=50, N=100, V=50000, D=512)
#define D_DIM 512
#define T_TGT 50
#define N_NOI 100
#define K_TOT 150
#define V_MAX 50000
#define MAX_B 4096
#define WPB   10            // warps per block
#define RPW   15            // rows per warp (10*15 = 150)
#define GRP   5             // pipeline group size (3 groups of 5)
#define NTHR  (WPB * 32)    // 320

// Scratch (__device__ globals: allocation APIs are forbidden)
__device__ signed char   g_Wq[(size_t)V_MAX * D_DIM];  // 25.6 MB int8 copy of W
__device__ float         g_Wscale[V_MAX];              // per-row W scale
__device__ signed char   g_fq[(size_t)MAX_B * D_DIM];  // int8 quantized features
__device__ float         g_fscale[MAX_B];              // per-example feature scale
__device__ float         g_partials[MAX_B];
__device__ int           g_idx_stride;                 // 1 = int32 indices, 2 = int64 low word
__device__ unsigned int  g_count;                      // zero-init; reset by last block each call

__device__ __forceinline__ float log_sigmoid(float x) {
    return fminf(x, 0.0f) - __logf(1.0f + __expf(-fabsf(x)));
}

__device__ __forceinline__ unsigned pack4(float x, float y, float z, float w, float inv) {
    int b0 = __float2int_rn(x * inv);
    int b1 = __float2int_rn(y * inv);
    int b2 = __float2int_rn(z * inv);
    int b3 = __float2int_rn(w * inv);
    return (unsigned)(b0 & 0xFF) | ((unsigned)(b1 & 0xFF) << 8) |
           ((unsigned)(b2 & 0xFF) << 16) | ((unsigned)b3 << 24);
}

// One warp quantizes one length-512 fp32 vector to int8 with a single scale.
// Lane owns elements [16*lane, 16*lane+16).
__device__ __forceinline__ void quant_row_warp(const float* __restrict__ src,
                                               signed char* __restrict__ dst,
                                               float* __restrict__ scale_out,
                                               int lane, bool streaming)
{
    const float4* s4 = reinterpret_cast<const float4*>(src);
    float4 v[4];
    #pragma unroll
    for (int j = 0; j < 4; j++)
        v[j] = streaming ? __ldcs(&s4[4 * lane + j]) : s4[4 * lane + j];

    float m = 0.0f;
    #pragma unroll
    for (int j = 0; j < 4; j++) {
        m = fmaxf(m, fabsf(v[j].x)); m = fmaxf(m, fabsf(v[j].y));
        m = fmaxf(m, fabsf(v[j].z)); m = fmaxf(m, fabsf(v[j].w));
    }
    #pragma unroll
    for (int o = 16; o > 0; o >>= 1)
        m = fmaxf(m, __shfl_xor_sync(0xFFFFFFFFu, m, o));

    const float inv = (m > 0.0f) ? 127.0f / m : 0.0f;

    uint4 o4;
    o4.x = pack4(v[0].x, v[0].y, v[0].z, v[0].w, inv);
    o4.y = pack4(v[1].x, v[1].y, v[1].z, v[1].w, inv);
    o4.z = pack4(v[2].x, v[2].y, v[2].z, v[2].w, inv);
    o4.w = pack4(v[3].x, v[3].y, v[3].z, v[3].w, inv);
    reinterpret_cast<uint4*>(dst)[lane] = o4;

    if (lane == 0)
        *scale_out = m * (1.0f / 127.0f);
}

// Blocks [0, nRowBlocks): quantize W rows. Blocks [nRowBlocks, ...): quantize features.
__global__ void __launch_bounds__(256)
nsl_convert_kernel(const float* __restrict__ W, const float* __restrict__ features,
                   const int* __restrict__ t32, int nRows, int nRowBlocks, int B)
{
    if (blockIdx.x == 0 && threadIdx.x == 0) {
        int all_zero = 1;
        #pragma unroll
        for (int i = 0; i < 8; i++)
            if (t32[2 * i + 1] != 0) all_zero = 0;
        g_idx_stride = all_zero ? 2 : 1;   // int64 little-endian => odd words are 0
    }

    const int warp = threadIdx.x >> 5;
    const int lane = threadIdx.x & 31;

    if ((int)blockIdx.x < nRowBlocks) {
        const int row = blockIdx.x * 8 + warp;
        if (row < nRows)
            quant_row_warp(W + (size_t)row * D_DIM,
                           g_Wq + (size_t)row * D_DIM,
                           &g_Wscale[row], lane, true);
    } else {
        const int ex = (blockIdx.x - nRowBlocks) * 8 + warp;
        if (ex < B)
            quant_row_warp(features + (size_t)ex * D_DIM,
                           g_fq + (size_t)ex * D_DIM,
                           &g_fscale[ex], lane, false);
    }
}

// 16 int8 x 16 int8 exact dot via 4 dp4a.
__device__ __forceinline__ int dot16(uint4 w, const int* fq) {
    int acc = 0;
    acc = __dp4a((int)w.x, fq[0], acc);
    acc = __dp4a((int)w.y, fq[1], acc);
    acc = __dp4a((int)w.z, fq[2], acc);
    acc = __dp4a((int)w.w, fq[3], acc);
    return acc;
}

// min-blocks=4 caps regs at ~51: enough for a 5-deep load pipeline, keeps occ ~62%.
__global__ void __launch_bounds__(NTHR, 4)
nsl_main_kernel(const int* __restrict__ targets,
                const int* __restrict__ noises,
                float* __restrict__ out, int B)
{
    const int b    = blockIdx.x;
    const int tid  = threadIdx.x;
    const int warp = tid >> 5;
    const int lane = tid & 31;
    const int str  = g_idx_stride;

    __shared__ float wsum[WPB];
    __shared__ int   is_last;

    // Prologue: one LDG.128 of pre-quantized features + one scalar scale load.
    int fq[4];
    {
        uint4 f = reinterpret_cast<const uint4*>(g_fq + (size_t)b * D_DIM)[lane];
        fq[0] = (int)f.x; fq[1] = (int)f.y; fq[2] = (int)f.z; fq[3] = (int)f.w;
    }
    const float sf = g_fscale[b];

    const int* tg = targets + (size_t)b * T_TGT * str;
    const int* ns = noises  + (size_t)b * N_NOI * str;

    // Warp w owns rows k in [15w, 15w+15). Lane r (r<15) preloads row 15w+r's index.
    int myidx = 0;
    if (lane < RPW) {
        int k = warp * RPW + lane;
        myidx = (k < T_TGT) ? tg[k * str] : ns[(k - T_TGT) * str];
    }

    // ---- Software-pipelined: 3 groups of 5 rows. Next group's loads issue
    // ---- before the current group's reduction chain, keeping LSU busy.
    uint4 buf[GRP];
    #pragma unroll
    for (int q = 0; q < GRP; q++) {
        int idx = __shfl_sync(0xFFFFFFFFu, myidx, q);
        buf[q] = __ldcg(&reinterpret_cast<const uint4*>(g_Wq + (size_t)idx * D_DIM)[lane]);
    }

    int v = 0;   // lane r (r<15) accumulates row r's total here
    #pragma unroll
    for (int g = 0; g < RPW / GRP; g++) {
        int sg[GRP];
        #pragma unroll
        for (int q = 0; q < GRP; q++)
            sg[q] = dot16(buf[q], fq);

        if (g < RPW / GRP - 1) {
            #pragma unroll
            for (int q = 0; q < GRP; q++) {
                int idx = __shfl_sync(0xFFFFFFFFu, myidx, GRP * (g + 1) + q);
                buf[q] = __ldcg(&reinterpret_cast<const uint4*>(g_Wq + (size_t)idx * D_DIM)[lane]);
            }
        }

        #pragma unroll
        for (int q = 0; q < GRP; q++) {
            int t = __reduce_add_sync(0xFFFFFFFFu, sg[q]);
            if (lane == GRP * g + q) v = t;
        }
    }

    // One parallel logsigmoid pass covers all 15 rows (lane r = row r).
    float local = 0.0f;
    if (lane < RPW) {
        float sw  = g_Wscale[myidx];          // this lane's own row index
        int   k   = warp * RPW + lane;
        float sgn = (k < T_TGT) ? 1.0f : -1.0f;
        local = log_sigmoid(sgn * (float)v * (sw * sf));
    }

    // Sum the 15 lane values within the warp.
    #pragma unroll
    for (int o = 16; o > 0; o >>= 1)
        local += __shfl_xor_sync(0xFFFFFFFFu, local, o);

    if (lane == 0) wsum[warp] = local;
    __syncthreads();

    if (tid == 0) {
        float sum = 0.0f;
        #pragma unroll
        for (int w = 0; w < WPB; w++) sum += wsum[w];
        g_partials[b] = sum;
        __threadfence();
        unsigned c = atomicAdd(&g_count, 1u);
        is_last = (c == (unsigned)(gridDim.x - 1)) ? 1 : 0;
    }
    __syncthreads();

    // Last finished block performs the deterministic final reduction (256 threads).
    if (is_last) {
        __shared__ float red[256];
        __threadfence();
        if (tid < 256) {
            float sum = 0.0f;
            for (int i = tid; i < B; i += 256)
                sum += g_partials[i];
            red[tid] = sum;
        }
        __syncthreads();
        #pragma unroll
        for (int stride = 128; stride > 0; stride >>= 1) {
            if (tid < stride) red[tid] += red[tid + stride];
            __syncthreads();
        }
        if (tid == 0) {
            out[0] = -red[0] / (float)K_TOT;
            g_count = 0;   // reset for next graph replay
        }
    }
}

extern "C" void kernel_launch(void* const* d_in, const int* in_sizes, int n_in,
                              void* d_out, int out_size)
{
    const float* features = (const float*)d_in[0];
    const int*   targets  = (const int*)d_in[1];
    const int*   noises   = (const int*)d_in[2];
    const float* W        = (const float*)d_in[3];

    const int B     = in_sizes[0] / D_DIM;        // 2048
    const int nRows = in_sizes[3] / D_DIM;        // 50000

    const int nRowBlocks = (nRows + 7) / 8;       // 6250
    const int nFeaBlocks = (B + 7) / 8;           // 256

    nsl_convert_kernel<<<nRowBlocks + nFeaBlocks, 256>>>(W, features, targets,
                                                         nRows, nRowBlocks, B);
    nsl_main_kernel<<<B, NTHR>>>(targets, noises, (float*)d_out, B);
}